// round 5
// baseline (speedup 1.0000x reference)
#include <cuda_runtime.h>

#define FULLMASK 0xffffffffu
typedef unsigned long long u64;

// ---------------------------------------------------------------------------
// State: amplitude index i (8 bits) = (r << 5) | lane. wire w <-> bit (7-w).
// Bits 0..4 lane, 5..7 register. a[8] packed complex: lo32=re, hi32=im.
// Per (layer,node) the 1q gate chain RY(theta)*ROT*G2_1q is FUSED into a single
// 2x2 matrix (uniform part precomputed in setup; per-sample RY folded at
// runtime) -> at most ONE lane exchange per node for the whole 1q chain.
// ---------------------------------------------------------------------------

__device__ __forceinline__ u64 pack2(float lo, float hi) {
    u64 r; asm("mov.b64 %0, {%1, %2};" : "=l"(r) : "f"(lo), "f"(hi)); return r;
}
__device__ __forceinline__ void unpack2(u64 v, float& lo, float& hi) {
    asm("mov.b64 {%0, %1}, %2;" : "=f"(lo), "=f"(hi) : "l"(v));
}
__device__ __forceinline__ u64 dup2(float x) { return pack2(x, x); }
__device__ __forceinline__ u64 fma2(u64 a, u64 b, u64 c) {
    u64 d; asm("fma.rn.f32x2 %0, %1, %2, %3;" : "=l"(d) : "l"(a), "l"(b), "l"(c)); return d;
}
__device__ __forceinline__ u64 mul2(u64 a, u64 b) {
    u64 d; asm("mul.rn.f32x2 %0, %1, %2;" : "=l"(d) : "l"(a), "l"(b)); return d;
}
__device__ __forceinline__ u64 swap2(u64 v) {
    float lo, hi; unpack2(v, lo, hi); return pack2(hi, lo);
}
template<int ML>
__device__ __forceinline__ u64 shfl2(u64 v) {
    float lo, hi; unpack2(v, lo, hi);
    lo = __shfl_xor_sync(FULLMASK, lo, ML);
    hi = __shfl_xor_sync(FULLMASK, hi, ML);
    return pack2(lo, hi);
}

// Complex coefficient in "apply form": r2 = (re,re), i2 = (-im,im).
struct CE { u64 r2, i2; };
__device__ __forceinline__ CE ce_make(float er, float ei) {
    CE o; o.r2 = dup2(er); o.i2 = pack2(-ei, ei); return o;
}
__device__ __forceinline__ CE ce_from(u64 e) {
    float er, ei; unpack2(e, er, ei); return ce_make(er, ei);
}
// v * m   (complex multiply, packed)
__device__ __forceinline__ u64 cmul(CE m, u64 v) {
    return fma2(m.i2, swap2(v), mul2(m.r2, v));
}
__device__ __forceinline__ u64 cmul_acc(CE m, u64 v, u64 acc) {
    return fma2(m.i2, swap2(v), fma2(m.r2, v, acc));
}

// ------------------------- fused 1q gate applies ---------------------------

// Real 2x2 [u00,u01;u10,u11]
template<int B>
__device__ __forceinline__ void ap_real(u64 a[8], int lane,
                                        float u00, float u01, float u10, float u11) {
    if constexpr (B >= 5) {
        constexpr int M = 1 << (B - 5);
        u64 c00 = dup2(u00), c01 = dup2(u01), c10 = dup2(u10), c11 = dup2(u11);
#pragma unroll
        for (int r = 0; r < 8; r++) {
            if ((r & M) == 0) {
                int r1 = r | M;
                u64 v0 = a[r], v1 = a[r1];
                a[r]  = fma2(c01, v1, mul2(c00, v0));
                a[r1] = fma2(c11, v1, mul2(c10, v0));
            }
        }
    } else {
        int bit = (lane >> B) & 1;
        u64 u = dup2(bit ? u11 : u00);
        u64 v = dup2(bit ? u10 : u01);
#pragma unroll
        for (int r = 0; r < 8; r++) {
            u64 p = shfl2<(1 << B)>(a[r]);
            a[r] = fma2(v, p, mul2(u, a[r]));
        }
    }
}

// Complex 2x2, entries packed (re,im)
template<int B>
__device__ __forceinline__ void ap_cplx(u64 a[8], int lane,
                                        u64 m00, u64 m01, u64 m10, u64 m11) {
    if constexpr (B >= 5) {
        constexpr int M = 1 << (B - 5);
        CE M00 = ce_from(m00), M01 = ce_from(m01), M10 = ce_from(m10), M11 = ce_from(m11);
#pragma unroll
        for (int r = 0; r < 8; r++) {
            if ((r & M) == 0) {
                int r1 = r | M;
                u64 v0 = a[r], v1 = a[r1];
                a[r]  = cmul_acc(M01, v1, cmul(M00, v0));
                a[r1] = cmul_acc(M11, v1, cmul(M10, v0));
            }
        }
    } else {
        int bit = (lane >> B) & 1;
        CE U = ce_from(bit ? m11 : m00);
        CE V = ce_from(bit ? m10 : m01);
#pragma unroll
        for (int r = 0; r < 8; r++) {
            u64 p = shfl2<(1 << B)>(a[r]);
            a[r] = cmul_acc(V, p, cmul(U, a[r]));
        }
    }
}

// Diagonal complex: a' = d(bit) * a  — zero shuffles.
template<int B>
__device__ __forceinline__ void ap_diag(u64 a[8], int lane,
                                        float d0r, float d0i, float d1r, float d1i) {
    if constexpr (B >= 5) {
        constexpr int M = 1 << (B - 5);
        CE D0 = ce_make(d0r, d0i), D1 = ce_make(d1r, d1i);
#pragma unroll
        for (int r = 0; r < 8; r++)
            a[r] = cmul((r & M) ? D1 : D0, a[r]);
    } else {
        int bit = (lane >> B) & 1;
        CE D = ce_make(bit ? d1r : d0r, bit ? d1i : d0i);
#pragma unroll
        for (int r = 0; r < 8; r++) a[r] = cmul(D, a[r]);
    }
}

// ------------------------- multi-qubit gates --------------------------------

// Controlled-X: flip bit T where all CM bits set.
template<int T, int CM>
__device__ __forceinline__ void g_cx(u64 a[8], int lane) {
    constexpr int CML = CM & 31;
    constexpr int CMR = (CM >> 5) & 7;
    bool lp = ((lane & CML) == CML);
    if constexpr (T < 5) {
#pragma unroll
        for (int r = 0; r < 8; r++) {
            if ((r & CMR) == CMR) {
                u64 p = shfl2<(1 << T)>(a[r]);
                if constexpr (CML == 0) a[r] = p;
                else a[r] = lp ? p : a[r];
            }
        }
    } else {
        constexpr int MT = 1 << (T - 5);
#pragma unroll
        for (int r = 0; r < 8; r++) {
            if (((r & CMR) == CMR) && !(r & MT)) {
                int r1 = r | MT;
                u64 v0 = a[r], v1 = a[r1];
                if constexpr (CML == 0) { a[r] = v1; a[r1] = v0; }
                else { a[r] = lp ? v1 : v0; a[r1] = lp ? v0 : v1; }
            }
        }
    }
}

// CZ on bits BA, BB
template<int BA, int BB>
__device__ __forceinline__ void g_cz(u64 a[8], int lane) {
    bool lp = true;
    if constexpr (BA < 5) lp = lp && (((lane >> BA) & 1) != 0);
    if constexpr (BB < 5) lp = lp && (((lane >> BB) & 1) != 0);
    u64 sg = dup2(lp ? -1.f : 1.f);
#pragma unroll
    for (int r = 0; r < 8; r++) {
        bool rp = true;
        if (BA >= 5) rp = rp && (((r >> (BA - 5)) & 1) != 0);
        if (BB >= 5) rp = rp && (((r >> (BB - 5)) & 1) != 0);
        if (rp) a[r] = mul2(sg, a[r]);
    }
}

template<int A, int Bb, int C>
__device__ __forceinline__ constexpr bool cswap_possible(int r) {
    bool possible = true;
    if (C >= 5 && !((r >> (C - 5)) & 1)) possible = false;
    if (A >= 5 && Bb >= 5 &&
        (((r >> (A - 5)) & 1) == ((r >> (Bb - 5)) & 1))) possible = false;
    return possible;
}

// CSWAP: control C; swap bits A,Bb where they differ. GATHER-THEN-UPDATE.
template<int A, int Bb, int C>
__device__ __forceinline__ void g_cswap(u64 a[8], int lane) {
    constexpr int M  = (1 << A) | (1 << Bb);
    constexpr int ML = M & 31;
    constexpr int MR = (M >> 5) & 7;
    u64 pa[8];
#pragma unroll
    for (int r = 0; r < 8; r++) {
        if (cswap_possible<A, Bb, C>(r)) {
            u64 v = a[r ^ MR];
            if constexpr (ML != 0) v = shfl2<ML>(v);
            pa[r] = v;
        }
    }
    bool lctl = true;
    if constexpr (C < 5) lctl = (((lane >> C) & 1) != 0);
#pragma unroll
    for (int r = 0; r < 8; r++) {
        if (cswap_possible<A, Bb, C>(r)) {
            int ba = (A  < 5) ? ((lane >> A)  & 1) : ((r >> (A  - 5)) & 1);
            int bb = (Bb < 5) ? ((lane >> Bb) & 1) : ((r >> (Bb - 5)) & 1);
            bool ctl = lctl;
            if (C >= 5) ctl = (((r >> (C - 5)) & 1) != 0);
            bool sw = ctl && (ba != bb);
            a[r] = sw ? pa[r] : a[r];
        }
    }
}

// ---------------------------------------------------------------------------
// Setup: per (layer,node) precompute A = G2_1q * ROT (complex 2x2), classify,
// pack into two float4 rows. Row0 = (A00r, A00i, A01r, A01i) with code in .w?
// Layout: g_mat[2i]   = (A00r, A00i, A01r, A01i)  -- but .w carries A01i: need
// separate code slot -> stash code in g_mat[2i+1].w (A11i never coexists with
// ...). A11i can be nonzero, so use a separate code array instead? No: pack
// code into row1.w is unsafe. Use: g_mat[2i] rows + g_code[i] int. Code load
// is an extra LDG.32 but L1-hot and warp-uniform.
// code bits: 0 = has_ry, [1:3) = atype (0 none,1 diag,2 real,3 cplx),
//            [3:7) = 2q/3q gate (0 or 5..8).
// ---------------------------------------------------------------------------
__device__ float4 g_mat[96];
__device__ int g_code[48];

struct C2 { float re, im; };
__device__ __forceinline__ C2 cxm(C2 a, C2 b) {   // a*b
    C2 o; o.re = a.re * b.re - a.im * b.im; o.im = a.re * b.im + a.im * b.re; return o;
}
__device__ __forceinline__ C2 cxa(C2 a, C2 b) { C2 o; o.re = a.re + b.re; o.im = a.im + b.im; return o; }

__global__ void setup_kernel(const float* __restrict__ qp,
                             const int* __restrict__ dry,
                             const int* __restrict__ drot,
                             const int* __restrict__ dg2) {
    int i = threadIdx.x;
    if (i >= 48) return;
    int layer = i >> 3, node = i & 7;
    int di = layer * 4 + (node & 3);
    float s, c;
    __sincosf(0.5f * qp[i], &s, &c);

    C2 A[2][2] = {{{1.f,0.f},{0.f,0.f}},{{0.f,0.f},{1.f,0.f}}};
    bool haveA = false;
    int rot = drot[di];
    if (rot == 0) {        // RX
        A[0][0] = {c,0.f}; A[0][1] = {0.f,-s}; A[1][0] = {0.f,-s}; A[1][1] = {c,0.f};
        haveA = true;
    } else if (rot == 1) { // RY
        A[0][0] = {c,0.f}; A[0][1] = {-s,0.f}; A[1][0] = {s,0.f};  A[1][1] = {c,0.f};
        haveA = true;
    } else if (rot == 2) { // RZ
        A[0][0] = {c,-s};  A[0][1] = {0.f,0.f}; A[1][0] = {0.f,0.f}; A[1][1] = {c,s};
        haveA = true;
    }
    int g2 = dg2[di];
    if (g2 >= 1 && g2 <= 4) {
        const float rh = 0.70710678118654752440f;
        C2 G[2][2];
        if (g2 == 1) {      // H
            G[0][0] = {rh,0.f}; G[0][1] = {rh,0.f}; G[1][0] = {rh,0.f}; G[1][1] = {-rh,0.f};
        } else if (g2 == 2) { // X
            G[0][0] = {0.f,0.f}; G[0][1] = {1.f,0.f}; G[1][0] = {1.f,0.f}; G[1][1] = {0.f,0.f};
        } else if (g2 == 3) { // Y
            G[0][0] = {0.f,0.f}; G[0][1] = {0.f,-1.f}; G[1][0] = {0.f,1.f}; G[1][1] = {0.f,0.f};
        } else {              // Z
            G[0][0] = {1.f,0.f}; G[0][1] = {0.f,0.f}; G[1][0] = {0.f,0.f}; G[1][1] = {-1.f,0.f};
        }
        C2 R[2][2];
        for (int r = 0; r < 2; r++)
            for (int cc = 0; cc < 2; cc++)
                R[r][cc] = cxa(cxm(G[r][0], A[0][cc]), cxm(G[r][1], A[1][cc]));
        A[0][0] = R[0][0]; A[0][1] = R[0][1]; A[1][0] = R[1][0]; A[1][1] = R[1][1];
        haveA = true;
    }
    int atype = 0;
    if (haveA) {
        bool offd  = (A[0][1].re != 0.f) || (A[0][1].im != 0.f) ||
                     (A[1][0].re != 0.f) || (A[1][0].im != 0.f);
        bool anyim = (A[0][0].im != 0.f) || (A[0][1].im != 0.f) ||
                     (A[1][0].im != 0.f) || (A[1][1].im != 0.f);
        atype = offd ? (anyim ? 3 : 2) : 1;   // diag (real or complex) -> 1
    }
    int code = (dry[di] & 1) | (atype << 1) | ((g2 >= 5 ? g2 : 0) << 3);
    g_code[i] = code;
    g_mat[2 * i]     = make_float4(A[0][0].re, A[0][0].im, A[0][1].re, A[0][1].im);
    g_mat[2 * i + 1] = make_float4(A[1][0].re, A[1][0].im, A[1][1].re, A[1][1].im);
}

// ---------------------------------------------------------------------------

template<int NODE>
__device__ __forceinline__ void do_node(u64 a[8], int lane, int layer,
                                        float fc_, float fs_) {
    constexpr int B  = 7 - NODE;
    constexpr int B1 = 7 - ((NODE + 1) & 7);
    constexpr int B2 = 7 - ((NODE + 2) & 7);

    const int idx = layer * 8 + NODE;
    int code = __ldg(&g_code[idx]);
    bool has_ry = (code & 1) != 0;
    int atype = (code >> 1) & 3;

    if (has_ry) {
        float c = __shfl_sync(FULLMASK, fc_, NODE);
        float s = __shfl_sync(FULLMASK, fs_, NODE);
        if (atype == 0) {
            ap_real<B>(a, lane, c, -s, s, c);                      // pure RY
        } else if (atype == 2) {
            float4 r0 = __ldg(&g_mat[2 * idx]);
            float4 r1 = __ldg(&g_mat[2 * idx + 1]);
            // M = A * RY(theta)  (real)
            float u00 = fmaf(r0.x, c,  r0.z * s);
            float u01 = fmaf(r0.z, c, -r0.x * s);
            float u10 = fmaf(r1.x, c,  r1.z * s);
            float u11 = fmaf(r1.z, c, -r1.x * s);
            ap_real<B>(a, lane, u00, u01, u10, u11);
        } else {
            float4 r0 = __ldg(&g_mat[2 * idx]);
            float4 r1 = __ldg(&g_mat[2 * idx + 1]);
            u64 A00 = pack2(r0.x, r0.y), A01 = pack2(r0.z, r0.w);
            u64 A10 = pack2(r1.x, r1.y), A11 = pack2(r1.z, r1.w);
            u64 c2 = dup2(c), s2 = dup2(s), ns2 = dup2(-s);
            u64 M00 = fma2(s2,  A01, mul2(c2,  A00));
            u64 M01 = fma2(c2,  A01, mul2(ns2, A00));
            u64 M10 = fma2(s2,  A11, mul2(c2,  A10));
            u64 M11 = fma2(c2,  A11, mul2(ns2, A10));
            ap_cplx<B>(a, lane, M00, M01, M10, M11);
        }
    } else if (atype) {
        float4 r0 = __ldg(&g_mat[2 * idx]);
        float4 r1 = __ldg(&g_mat[2 * idx + 1]);
        if (atype == 1) {
            ap_diag<B>(a, lane, r0.x, r0.y, r1.z, r1.w);
        } else if (atype == 2) {
            ap_real<B>(a, lane, r0.x, r0.z, r1.x, r1.z);
        } else {
            ap_cplx<B>(a, lane, pack2(r0.x, r0.y), pack2(r0.z, r0.w),
                                pack2(r1.x, r1.y), pack2(r1.z, r1.w));
        }
    }

    int g2 = (code >> 3) & 15;
    if (g2) {
        switch (g2) {
            case 5: g_cx<B1, (1 << B)>(a, lane); break;              // CNOT
            case 6: g_cswap<B1, B2, B>(a, lane); break;              // CSWAP
            case 7: g_cx<B2, (1 << B) | (1 << B1)>(a, lane); break;  // Toffoli
            case 8: g_cz<B, B1>(a, lane); break;                     // CZ
            default: break;
        }
    }
}

__global__ void __launch_bounds__(256) qsim_kernel(
    const float* __restrict__ feats,   // [B, 8]
    float* __restrict__ out,           // [B, 8]
    int batch) {
    int w = (int)((blockIdx.x * blockDim.x + threadIdx.x) >> 5);
    int lane = threadIdx.x & 31;
    if (w >= batch) return;

    float fv = feats[w * 8 + (lane & 7)];
    float fs_, fc_;
    __sincosf(0.5f * fv, &fs_, &fc_);

    // H^8 |0...0>  ==  uniform 1/16 real amplitude
    u64 a[8];
    u64 init = pack2(0.0625f, 0.0f);
#pragma unroll
    for (int r = 0; r < 8; r++) a[r] = init;

#pragma unroll 1
    for (int layer = 0; layer < 6; ++layer) {
        do_node<0>(a, lane, layer, fc_, fs_);
        do_node<1>(a, lane, layer, fc_, fs_);
        do_node<2>(a, lane, layer, fc_, fs_);
        do_node<3>(a, lane, layer, fc_, fs_);
        do_node<4>(a, lane, layer, fc_, fs_);
        do_node<5>(a, lane, layer, fc_, fs_);
        do_node<6>(a, lane, layer, fc_, fs_);
        do_node<7>(a, lane, layer, fc_, fs_);
    }

    // Measurement: <Z_p> = sum_i |a_i|^2 * (1 - 2*bit_{7-p}(i)),  i = (r<<5)|lane
    float acc[8];
#pragma unroll
    for (int p = 0; p < 8; p++) acc[p] = 0.f;
    float sgl[8];
#pragma unroll
    for (int p = 3; p < 8; p++)
        sgl[p] = ((lane >> (7 - p)) & 1) ? -1.f : 1.f;
#pragma unroll
    for (int r = 0; r < 8; r++) {
        float re, im;
        unpack2(a[r], re, im);
        float pr = fmaf(re, re, im * im);
        acc[0] += ((r >> 2) & 1) ? -pr : pr;
        acc[1] += ((r >> 1) & 1) ? -pr : pr;
        acc[2] += (r & 1)        ? -pr : pr;
#pragma unroll
        for (int p = 3; p < 8; p++) acc[p] += sgl[p] * pr;
    }
#pragma unroll
    for (int p = 0; p < 8; p++) {
#pragma unroll
        for (int off = 16; off; off >>= 1)
            acc[p] += __shfl_xor_sync(FULLMASK, acc[p], off);
    }
    if (lane == 0) {
        float4* o = reinterpret_cast<float4*>(out + (size_t)w * 8);
        o[0] = make_float4(acc[0], acc[1], acc[2], acc[3]);
        o[1] = make_float4(acc[4], acc[5], acc[6], acc[7]);
    }
}

extern "C" void kernel_launch(void* const* d_in, const int* in_sizes, int n_in,
                              void* d_out, int out_size) {
    const float* feats = (const float*)d_in[0];   // [B, 8] float32
    const float* qp    = (const float*)d_in[1];   // [48]  float32
    const int* dry     = (const int*)d_in[2];     // [6,4] int32
    const int* drot    = (const int*)d_in[3];     // [6,4] int32
    const int* dg2     = (const int*)d_in[4];     // [6,4] int32
    float* out         = (float*)d_out;           // [B, 8] float32

    int batch = in_sizes[0] / 8;
    setup_kernel<<<1, 64>>>(qp, dry, drot, dg2);
    int threads = 256;
    int total_threads = batch * 32;
    int blocks = (total_threads + threads - 1) / threads;
    qsim_kernel<<<blocks, threads>>>(feats, out, batch);
}